// round 14
// baseline (speedup 1.0000x reference)
#include <cuda_runtime.h>
#include <cuda_bf16.h>
#include <math.h>

// Problem constants
#define BB 64
#define HH 1024
#define EE 512
#define VV 32000
#define TENC 64
#define STEPS 32
#define KOUT 2048   // 2*H

typedef unsigned long long ull;
typedef unsigned int u32;

// ---------------- scratch (device globals; no allocation allowed) ----------
__device__ float g_a0[BB * 192];
__device__ float g_h[BB * HH];            // fp32 master hidden state
__device__ float g_gip[4][BB * 3 * HH];   // split-K partials of x @ W_ih^T
__device__ float g_ghp[8][BB * 3 * HH];   // split-K partials of h @ W_hh^T
__device__ float g_ewa[BB * TENC * HH];   // precomputed enc @ W_a^T (fp32)
__device__ ull   g_amax[BB];              // packed (key, 0x7FFFFFFF-n) argmax

// Tiled+swizzled activations: [kchunk][64 rows x 128B(32hi|32lo)] = 8KB blocks
__device__ __align__(16) __nv_bfloat16 g_xt[BB * EE * 2];        // 16 chunks
__device__ __align__(16) __nv_bfloat16 g_ht[BB * HH * 2];        // 32 chunks
__device__ __align__(16) __nv_bfloat16 g_vt[BB * KOUT * 2];      // 64 chunks
__device__ __align__(16) __nv_bfloat16 g_et[BB * TENC * HH * 2]; // enc, per-batch 32 chunks

// Tiled+swizzled weights: [ntile][kchunk][128 rows x 128B(32hi|32lo)] = 16KB blocks
__device__ __align__(16) __nv_bfloat16 g_Wih[3 * HH * 2 * EE];
__device__ __align__(16) __nv_bfloat16 g_Whh[3 * HH * 2 * HH];
__device__ __align__(16) __nv_bfloat16 g_Wa[HH * 2 * HH];        // B[n=k_out][k=h] = W_a
__device__ __align__(16) __nv_bfloat16 g_Wout[(size_t)VV * 2 * KOUT];

// ====================== PTX helpers ========================================
__device__ __forceinline__ u32 smem_u32(const void* p) {
    u32 a;
    asm("{ .reg .u64 t; cvta.to.shared.u64 t, %1; cvt.u32.u64 %0, t; }"
        : "=r"(a) : "l"(p));
    return a;
}
#define MBAR_INIT(a, c) \
    asm volatile("mbarrier.init.shared.b64 [%0], %1;" :: "r"(a), "r"(c) : "memory")
#define MBAR_EXPECT(a, b) \
    asm volatile("mbarrier.arrive.expect_tx.shared.b64 _, [%0], %1;" :: "r"(a), "r"(b) : "memory")
#define MBAR_ARRIVE(a) \
    asm volatile("mbarrier.arrive.shared.b64 _, [%0];" :: "r"(a) : "memory")
#define FENCE_ASYNC() \
    asm volatile("fence.proxy.async.shared::cta;" ::: "memory")
#define BULK_G2S(dst, src, sz, mb) \
    asm volatile("cp.async.bulk.shared::cluster.global.mbarrier::complete_tx::bytes " \
                 "[%0], [%1], %2, [%3];" \
                 :: "r"(dst), "l"(src), "r"(sz), "r"(mb) : "memory")

__device__ __forceinline__ void mbar_wait(u32 addr, u32 parity) {
    asm volatile(
        "{\n\t.reg .pred P;\n\t"
        "W%=:\n\t"
        "mbarrier.try_wait.parity.shared.b64 P, [%0], %1;\n\t"
        "@P bra D%=;\n\t"
        "bra W%=;\n\t"
        "D%=:\n\t}"
        :: "r"(addr), "r"(parity) : "memory");
}
__device__ __forceinline__ void ldmx4(u32* r, u32 addr) {
    asm volatile("ldmatrix.sync.aligned.m8n8.x4.shared.b16 {%0,%1,%2,%3}, [%4];"
                 : "=r"(r[0]), "=r"(r[1]), "=r"(r[2]), "=r"(r[3]) : "r"(addr));
}
__device__ __forceinline__ void mma16816(float* c, const u32* a, const u32* b) {
    asm volatile(
        "mma.sync.aligned.m16n8k16.row.col.f32.bf16.bf16.f32 "
        "{%0,%1,%2,%3}, {%4,%5,%6,%7}, {%8,%9}, {%0,%1,%2,%3};"
        : "+f"(c[0]), "+f"(c[1]), "+f"(c[2]), "+f"(c[3])
        : "r"(a[0]), "r"(a[1]), "r"(a[2]), "r"(a[3]), "r"(b[0]), "r"(b[1]));
}

// packed argmax key: monotone float map in hi 32, (0x7FFFFFFF - n) in lo 32
__device__ __forceinline__ ull amax_pack(float v, int n) {
    u32 b = __float_as_uint(v);
    u32 key = (b & 0x80000000u) ? ~b : (b | 0x80000000u);
    return ((ull)key << 32) | (ull)(0x7FFFFFFFu - (u32)n);
}

// ===========================================================================
// Split-bf16 HMMA GEMM body (544 threads = 16 consumer warps + 1 producer):
//   C[64, N] = (Ah+Al)[64,Klen] @ (Bh+Bl)[N,Klen]^T (+ bias)
//   = Ah·Bh + Al·Bh + Ah·Bl  (Al·Bl dropped, ~2^-16 relative)
// A/B pre-tiled + SW128-swizzled in GMEM; loaded via 2 cp.async.bulk per stage.
// 4-stage pipeline, full/empty mbarriers; warp 16 lane 0 is dedicated producer.
// CTA tile 64 x 128; consumer warp grid 2m x 8n; warp tile 32 x 16. nk >= 4.
// AM=1: additionally computes per-row argmax of biased output into g_amax.
// ===========================================================================
#define ABLK 8192
#define BBLK 16384
#define STGSZ (ABLK + BBLK)                 // 24576
#define NSTG 4
#define GM_SMEM (NSTG * STGSZ + 64 + 512)   // stages + mbarriers + best[64]

template <int AM>
__device__ __forceinline__ void gemm_body(
    const __nv_bfloat16* __restrict__ At, const __nv_bfloat16* __restrict__ Bt,
    const float* __restrict__ bias, float* __restrict__ C,
    long ldc, int nk, int nkTot, int kcBase, int ntile, char* smem)
{
    const u32 sb = smem_u32(smem);
    const u32 mbF = sb + NSTG * STGSZ;   // full[0..3], 8B each
    const u32 mbE = mbF + 32;            // empty[0..3]
    const int tid = threadIdx.x, wid = tid >> 5, lane = tid & 31;
    const int wm = (wid & 1) * 32;       // warp m offset: 0 or 32
    const int wn = (wid >> 1) * 16;      // warp n offset: 0..112
    const int n_cta = ntile * 128;

    if (tid == 0) {
#pragma unroll
        for (int s = 0; s < NSTG; s++) {
            MBAR_INIT(mbF + 8 * s, 1);
            MBAR_INIT(mbE + 8 * s, 16);
        }
    }
    FENCE_ASYNC();
    __syncthreads();

    float acc[2][2][4] = {};

    if (wid == 16) {
        // ---------------- producer warp (lane 0 only) ----------------
        if (lane == 0) {
            const char* Ab = (const char*)At + (size_t)kcBase * ABLK;
            const char* Bb = (const char*)Bt + ((size_t)ntile * nkTot + kcBase) * BBLK;
            for (int j = 0; j < nk; j++) {
                const int s = j & (NSTG - 1);
                if (j >= NSTG) mbar_wait(mbE + 8 * s, ((j - NSTG) >> 2) & 1);
                u32 m = mbF + 8 * s;
                MBAR_EXPECT(m, STGSZ);
                BULK_G2S(sb + s * STGSZ,        Ab + (size_t)j * ABLK, ABLK, m);
                BULK_G2S(sb + s * STGSZ + ABLK, Bb + (size_t)j * BBLK, BBLK, m);
            }
        }
    } else {
        // ---------------- consumer warps ----------------
        const int lrow = lane & 15;
        const int lkof = (lane >> 4) * 16;
        const int a0r = wm + lrow,  a1r = wm + 16 + lrow,  brr = wn + lrow;
        const u32 a0b = a0r * 128,  a0x = (a0r & 7) << 4;
        const u32 a1b = a1r * 128,  a1x = (a1r & 7) << 4;
        const u32 brb = brr * 128,  brx = (brr & 7) << 4;

        for (int j = 0; j < nk; j++) {
            const int s = j & (NSTG - 1);
            mbar_wait(mbF + 8 * s, (j >> 2) & 1);

            const u32 bbA = sb + s * STGSZ;
            const u32 bbB = bbA + ABLK;
#pragma unroll
            for (int ks = 0; ks < 2; ks++) {
                const u32 o = ks * 32 + lkof;
                u32 ah[2][4], al[2][4], bh[4], bl[4];
                ldmx4(ah[0], bbA + a0b + (o ^ a0x));
                ldmx4(ah[1], bbA + a1b + (o ^ a1x));
                ldmx4(al[0], bbA + a0b + ((o + 64) ^ a0x));
                ldmx4(al[1], bbA + a1b + ((o + 64) ^ a1x));
                ldmx4(bh,    bbB + brb + (o ^ brx));
                ldmx4(bl,    bbB + brb + ((o + 64) ^ brx));

                u32 b0h[2] = { bh[0], bh[2] };
                u32 b1h[2] = { bh[1], bh[3] };
                u32 b0l[2] = { bl[0], bl[2] };
                u32 b1l[2] = { bl[1], bl[3] };
#pragma unroll
                for (int mt = 0; mt < 2; mt++) {
                    float* c0 = acc[mt][0];
                    float* c1 = acc[mt][1];
                    mma16816(c0, ah[mt], b0h);
                    mma16816(c1, ah[mt], b1h);
                    mma16816(c0, al[mt], b0h);
                    mma16816(c1, al[mt], b1h);
                    mma16816(c0, ah[mt], b0l);
                    mma16816(c1, ah[mt], b1l);
                }
            }
            if (lane == 0) MBAR_ARRIVE(mbE + 8 * s);
        }
    }

    // ------------- epilogue -------------
    ull* best = reinterpret_cast<ull*>(smem + NSTG * STGSZ + 64);
    if (AM) {
        if (tid < 64) best[tid] = 0;
        __syncthreads();
    }

    if (wid < 16) {
#pragma unroll
        for (int mt = 0; mt < 2; mt++) {
            int m = wm + mt * 16 + (lane >> 2);
            ull p0 = 0, p1 = 0;
#pragma unroll
            for (int t = 0; t < 2; t++) {
                int n = n_cta + wn + t * 8 + 2 * (lane & 3);
                float* a = acc[mt][t];
                float b0 = bias ? bias[n] : 0.f;
                float b1 = bias ? bias[n + 1] : 0.f;
                float2 v0 = { a[0] + b0, a[1] + b1 };
                float2 v1 = { a[2] + b0, a[3] + b1 };
                *reinterpret_cast<float2*>(C + (size_t)m * ldc + n) = v0;
                *reinterpret_cast<float2*>(C + (size_t)(m + 8) * ldc + n) = v1;
                if (AM) {
                    ull q0 = amax_pack(v0.x, n), q1 = amax_pack(v0.y, n + 1);
                    p0 = max(p0, max(q0, q1));
                    ull q2 = amax_pack(v1.x, n), q3 = amax_pack(v1.y, n + 1);
                    p1 = max(p1, max(q2, q3));
                }
            }
            if (AM) {
#pragma unroll
                for (int o = 1; o < 4; o <<= 1) {
                    p0 = max(p0, __shfl_xor_sync(0xFFFFFFFFu, p0, o));
                    p1 = max(p1, __shfl_xor_sync(0xFFFFFFFFu, p1, o));
                }
                if ((lane & 3) == 0) {
                    atomicMax(&best[m], p0);
                    atomicMax(&best[m + 8], p1);
                }
            }
        }
    }
    if (AM) {
        __syncthreads();
        if (tid < 64) atomicMax(&g_amax[tid], best[tid]);
    }
}

// logits GEMM: 250 CTAs, fused argmax
__global__ __launch_bounds__(544, 2)
void gemm_logits(const __nv_bfloat16* __restrict__ At, const __nv_bfloat16* __restrict__ Bt,
                 const float* __restrict__ bias, float* __restrict__ C, long ldc)
{
    extern __shared__ char smem[];
    gemm_body<1>(At, Bt, bias, C, ldc, KOUT / 32, KOUT / 32, 0, blockIdx.x, smem);
}

// enc_wa precompute: 64 batches x 8 ntiles = 512 CTAs (one-time)
__global__ __launch_bounds__(544, 2)
void gemm_encwa(const __nv_bfloat16* __restrict__ et, const __nv_bfloat16* __restrict__ Wa)
{
    extern __shared__ char smem[];
    int b = blockIdx.x >> 3, nt = blockIdx.x & 7;
    gemm_body<0>(et + (size_t)b * TENC * HH * 2, Wa, nullptr,
                 g_ewa + (size_t)b * TENC * HH, HH, HH / 32, HH / 32, 0, nt, smem);
}

// fused gi + gh: gi 4-way split (96 CTAs), gh 8-way split (192 CTAs) = 288 CTAs
__global__ __launch_bounds__(544, 2)
void gemm_gigh(const __nv_bfloat16* __restrict__ xt, const __nv_bfloat16* __restrict__ Wih,
               const __nv_bfloat16* __restrict__ ht, const __nv_bfloat16* __restrict__ Whh)
{
    extern __shared__ char smem[];
    int bid = blockIdx.x;
    if (bid < 96) {
        int s = bid / 24, nt = bid % 24;   // gi: K=512 -> 4 slices x 4 chunks
        gemm_body<0>(xt, Wih, nullptr, g_gip[s], 3 * HH, 4, EE / 32, s * 4, nt, smem);
    } else {
        bid -= 96;
        int s = bid / 24, nt = bid % 24;   // gh: K=1024 -> 8 slices x 4 chunks
        gemm_body<0>(ht, Whh, nullptr, g_ghp[s], 3 * HH, 4, HH / 32, s * 4, nt, smem);
    }
}

// ===================== split + tiled-store helpers =========================
__device__ __forceinline__ void split2(float v, __nv_bfloat16& h, __nv_bfloat16& l) {
    h = __float2bfloat16(v);
    l = __float2bfloat16(v - __bfloat162float(h));
}

// store one activation element into tiled+swizzled layout (8KB A-blocks)
__device__ __forceinline__ void store_act(__nv_bfloat16* base, int kc, int r, int c, float v) {
    __nv_bfloat16 h, l; split2(v, h, l);
    u32 xm = (r & 7) << 4;
    char* p = (char*)base + (size_t)kc * ABLK + r * 128;
    *reinterpret_cast<__nv_bfloat16*>(p + ((c * 2) ^ xm)) = h;
    *reinterpret_cast<__nv_bfloat16*>(p + ((64 + c * 2) ^ xm)) = l;
}

// store one weight element into tiled+swizzled layout (16KB B-blocks)
__device__ __forceinline__ void store_w(__nv_bfloat16* base, int nkTot, int n, int k, float v) {
    __nv_bfloat16 h, l; split2(v, h, l);
    int nt = n >> 7, r = n & 127, kc = k >> 5, c = k & 31;
    u32 xm = (r & 7) << 4;
    char* p = (char*)base + ((size_t)nt * nkTot + kc) * BBLK + r * 128;
    *reinterpret_cast<__nv_bfloat16*>(p + ((c * 2) ^ xm)) = h;
    *reinterpret_cast<__nv_bfloat16*>(p + ((64 + c * 2) ^ xm)) = l;
}

// elementwise: src already [N,K]
__device__ __forceinline__ void esplit_blk(const float* src, __nv_bfloat16* dc,
                                           int K, int bi, int tid)
{
    int i = bi * 256 + tid;
    store_w(dc, K >> 5, i / K, i % K, src[i]);
}

// transpose 32x32 tile: src [K,N] fp32 -> tiled [N-major] layout
__device__ __forceinline__ void tsplit_blk(const float* src, __nv_bfloat16* dc,
                                           int K, int N, int bx, int by, int tid)
{
    __shared__ float t[32][33];
    int k0 = by * 32, n0 = bx * 32;
    int tx = tid & 31, ty = tid >> 5;   // 32 x 8
#pragma unroll
    for (int i = ty; i < 32; i += 8)
        t[i][tx] = src[(size_t)(k0 + i) * N + n0 + tx];
    __syncthreads();
#pragma unroll
    for (int i = ty; i < 32; i += 8)
        store_w(dc, K >> 5, n0 + i, k0 + tx, t[tx][i]);
}

#define NB_WIH  6144    // 3*HH*EE / 256
#define NB_WHH 12288    // 3*HH*HH / 256
#define NB_WA   4096    // HH*HH / 256 (esplit — W_a used un-transposed)
#define NB_WOUT 64000   // (VV/32)*(KOUT/32)
#define NB_ENC  16384   // BB*TENC*HH / 256
#define NB_CONV (NB_WIH + NB_WHH + NB_WA + NB_WOUT + NB_ENC)

__global__ __launch_bounds__(256)
void convert_all(const float* __restrict__ W_ih, const float* __restrict__ W_hh,
                 const float* __restrict__ W_a,  const float* __restrict__ W_out,
                 const float* __restrict__ enc)
{
    int b = blockIdx.x, tid = threadIdx.x;
    if (b < NB_WIH) {
        esplit_blk(W_ih, g_Wih, EE, b, tid);
    } else if (b < NB_WIH + NB_WHH) {
        esplit_blk(W_hh, g_Whh, HH, b - NB_WIH, tid);
    } else if (b < NB_WIH + NB_WHH + NB_WA) {
        esplit_blk(W_a, g_Wa, HH, b - NB_WIH - NB_WHH, tid);
    } else if (b < NB_WIH + NB_WHH + NB_WA + NB_WOUT) {
        int bi = b - NB_WIH - NB_WHH - NB_WA;
        tsplit_blk(W_out, g_Wout, KOUT, VV, bi % (VV / 32), bi / (VV / 32), tid);
    } else {
        // enc -> per-batch tiled act layout
        int i = (b - NB_WIH - NB_WHH - NB_WA - NB_WOUT) * 256 + tid;
        int bb = i >> 16;            // TENC*HH = 65536
        int rem = i & 65535;
        int t = rem >> 10, h = rem & 1023;
        store_act(g_et + (size_t)bb * TENC * HH * 2, h >> 5, t, h & 31, enc[i]);
    }
}

// ======================= init kernels ======================================
__global__ void build_init(const float* __restrict__ latent,
                           const int* __restrict__ style,
                           const float* __restrict__ style_emb,
                           const float* __restrict__ emb)
{
    int idx = blockIdx.x * blockDim.x + threadIdx.x;
    if (idx < BB * 192) {
        int b = idx / 192, k = idx - b * 192;
        g_a0[idx] = (k < 128) ? latent[b * 128 + k]
                              : style_emb[style[b] * 64 + (k - 128)];
    } else {
        int i = idx - BB * 192;
        if (i < BB * EE) {
            int b = i >> 9, e = i & (EE - 1);
            float v = emb[EE /* BOS=1 row */ + e];
            store_act(g_xt, e >> 5, b, e & 31, v);
        }
    }
}

// h = a0 @ W_l2h + b (fp32 FFMA; also emits tiled split-bf16 h)
__global__ __launch_bounds__(128)
void gemm_init(const float* __restrict__ A, int lda,
               const float* __restrict__ Bm, const float* __restrict__ bias,
               float* __restrict__ C, int N, int K)
{
    __shared__ float As[16][68];
    __shared__ float Bs[16][132];
    const int tid = threadIdx.x;
    const int n0 = blockIdx.x * 128;
    const int tm = (tid >> 4) << 3, tn = (tid & 15) << 3;
    float acc[8][8] = {};
    for (int k0 = 0; k0 < K; k0 += 16) {
        {
            int k = tid & 15, m = tid >> 4;
#pragma unroll
            for (int i = 0; i < 8; i++)
                As[k][m + i * 8] = A[(m + i * 8) * lda + k0 + k];
        }
        {
            int w = tid >> 5, n4 = (tid & 31) << 2;
#pragma unroll
            for (int kb = 0; kb < 4; kb++) {
                int k = kb * 4 + w;
                *reinterpret_cast<float4*>(&Bs[k][n4]) =
                    *reinterpret_cast<const float4*>(&Bm[(size_t)(k0 + k) * N + n0 + n4]);
            }
        }
        __syncthreads();
#pragma unroll
        for (int kk = 0; kk < 16; kk++) {
#pragma unroll
            for (int i = 0; i < 8; i++) {
                float a = As[kk][tm + i];
#pragma unroll
                for (int j = 0; j < 8; j++) acc[i][j] += a * Bs[kk][tn + j];
            }
        }
        __syncthreads();
    }
#pragma unroll
    for (int i = 0; i < 8; i++)
#pragma unroll
        for (int j = 0; j < 8; j++) {
            int n = n0 + tn + j;
            float v = acc[i][j] + (bias ? bias[n] : 0.f);
            int m = tm + i;
            C[(size_t)m * N + n] = v;
            store_act(g_ht, n >> 5, m, n & 31, v);
        }
}

// ========================= fused GRU + attention ==========================
// 64 CTAs (one per batch), 512 threads. Computes h_new, then scores via
// precomputed enc_wa, softmax, ctx; fills g_ht and g_vt. Resets g_amax.
__global__ __launch_bounds__(512)
void gru_attn(const float* __restrict__ b_ih, const float* __restrict__ b_hh,
              const float* __restrict__ enc)
{
    int b = blockIdx.x;
    int tid = threadIdx.x;              // 512
    __shared__ float s_h[HH];
    __shared__ float s_scores[TENC];
    __shared__ float s_attn[TENC];

    if (tid == 0) g_amax[b] = 0;        // reset fused-argmax slot for this step

    for (int j = tid; j < HH; j += 512) {
        int idx = b * HH + j;
        int base = b * 3 * HH + j;
        float ir = b_ih[j], iz = b_ih[j + HH], in = b_ih[j + 2 * HH];
        float hr = b_hh[j], hz = b_hh[j + HH], hn = b_hh[j + 2 * HH];
#pragma unroll
        for (int s = 0; s < 4; s++) {
            ir += g_gip[s][base];
            iz += g_gip[s][base + HH];
            in += g_gip[s][base + 2 * HH];
        }
#pragma unroll
        for (int s = 0; s < 8; s++) {
            hr += g_ghp[s][base];
            hz += g_ghp[s][base + HH];
            hn += g_ghp[s][base + 2 * HH];
        }
        float r = 1.f / (1.f + expf(-(ir + hr)));
        float z = 1.f / (1.f + expf(-(iz + hz)));
        float n = tanhf(in + r * hn);
        float hnew = (1.f - z) * n + z * g_h[idx];
        g_h[idx] = hnew;
        int kc = j >> 5, c = j & 31;
        store_act(g_ht, kc, b, c, hnew);
        store_act(g_vt, kc, b, c, hnew);   // vcat chunks 0..31 = h
        s_h[j] = hnew;
    }
    __syncthreads();

    int warp = tid >> 5, lane = tid & 31;
    for (int t = warp; t < TENC; t += 16) {
        const float* e = g_ewa + ((size_t)b * TENC + t) * HH;
        float s = 0.f;
        for (int k = lane; k < HH; k += 32) s += s_h[k] * e[k];
#pragma unroll
        for (int o = 16; o; o >>= 1) s += __shfl_xor_sync(0xFFFFFFFFu, s, o);
        if (lane == 0) s_scores[t] = s;
    }
    __syncthreads();

    float mx = -1e30f;
    for (int t = 0; t < TENC; t++) mx = fmaxf(mx, s_scores[t]);
    if (tid < TENC) s_attn[tid] = expf(s_scores[tid] - mx);
    __syncthreads();
    float ssum = 0.f;
    for (int t = 0; t < TENC; t++) ssum += s_attn[t];
    float inv = 1.f / ssum;

    for (int h = tid; h < HH; h += 512) {
        float c = 0.f;
        const float* eb = enc + (size_t)b * TENC * HH + h;
#pragma unroll 8
        for (int t = 0; t < TENC; t++) c += s_attn[t] * eb[(size_t)t * HH];
        c *= inv;
        store_act(g_vt, 32 + (h >> 5), b, h & 31, c);   // vcat chunks 32..63 = ctx
    }
}

// decode g_amax -> token, gather embedding into g_xt
__global__ __launch_bounds__(128)
void embed_next(const float* __restrict__ emb)
{
    int b = blockIdx.x;
    int tid = threadIdx.x;
    int tok = 0x7FFFFFFF - (int)(u32)(g_amax[b] & 0xFFFFFFFFull);
    for (int e = tid; e < EE; e += 128) {
        float v = emb[(size_t)tok * EE + e];
        store_act(g_xt, e >> 5, b, e & 31, v);
    }
}

// ===========================================================================
extern "C" void kernel_launch(void* const* d_in, const int* in_sizes, int n_in,
                              void* d_out, int out_size)
{
    const float* latent    = (const float*)d_in[0];
    const int*   style     = (const int*)  d_in[1];
    const float* enc       = (const float*)d_in[2];
    const float* emb       = (const float*)d_in[4];
    const float* style_emb = (const float*)d_in[5];
    const float* W_l2h     = (const float*)d_in[6];
    const float* b_l2h     = (const float*)d_in[7];
    const float* W_ih      = (const float*)d_in[8];
    const float* W_hh      = (const float*)d_in[9];
    const float* b_ih      = (const float*)d_in[10];
    const float* b_hh      = (const float*)d_in[11];
    const float* W_a       = (const float*)d_in[12];
    const float* W_out     = (const float*)d_in[13];
    const float* b_out     = (const float*)d_in[14];
    float* out = (float*)d_out;

    cudaFuncSetAttribute(gemm_logits, cudaFuncAttributeMaxDynamicSharedMemorySize, GM_SMEM);
    cudaFuncSetAttribute(gemm_encwa,  cudaFuncAttributeMaxDynamicSharedMemorySize, GM_SMEM);
    cudaFuncSetAttribute(gemm_gigh,   cudaFuncAttributeMaxDynamicSharedMemorySize, GM_SMEM);

    __nv_bfloat16 *pWih, *pWhh, *pWa, *pWout, *pxt, *pht, *pvt, *pet;
    float *p_a0, *p_h;
    cudaGetSymbolAddress((void**)&pWih,  g_Wih);
    cudaGetSymbolAddress((void**)&pWhh,  g_Whh);
    cudaGetSymbolAddress((void**)&pWa,   g_Wa);
    cudaGetSymbolAddress((void**)&pWout, g_Wout);
    cudaGetSymbolAddress((void**)&pxt,   g_xt);
    cudaGetSymbolAddress((void**)&pht,   g_ht);
    cudaGetSymbolAddress((void**)&pvt,   g_vt);
    cudaGetSymbolAddress((void**)&pet,   g_et);
    cudaGetSymbolAddress((void**)&p_a0,  g_a0);
    cudaGetSymbolAddress((void**)&p_h,   g_h);

    // launch 0: all weight + enc conversion (tiled + swizzled layout)
    convert_all<<<NB_CONV, 256>>>(W_ih, W_hh, W_a, W_out, enc);
    // launch 1: one-time enc_wa = enc @ W_a^T
    gemm_encwa<<<BB * 8, 544, GM_SMEM>>>(pet, pWa);
    // launch 2: a0 + x0
    build_init<<<(BB * 192 + BB * EE + 255) / 256, 256>>>(latent, style, style_emb, emb);
    // launch 3: h init (+ tiled split)
    gemm_init<<<HH / 128, 128>>>(p_a0, 192, W_l2h, b_l2h, p_h, HH, 192);

    // decode loop: 4 kernels per step
    for (int t = 0; t < STEPS; t++) {
        gemm_gigh<<<288, 544, GM_SMEM>>>(pxt, pWih, pht, pWhh);
        gru_attn<<<BB, 512>>>(b_ih, b_hh, enc);
        gemm_logits<<<VV / 128, 544, GM_SMEM>>>(pvt, pWout, b_out,
                                                out + (size_t)t * VV, (long)STEPS * VV);
        if (t < STEPS - 1) embed_next<<<BB, 128>>>(emb);
    }
}

// round 16
// speedup vs baseline: 1.0824x; 1.0824x over previous
#include <cuda_runtime.h>
#include <cuda_bf16.h>
#include <math.h>

// Problem constants
#define BB 64
#define HH 1024
#define EE 512
#define VV 32000
#define TENC 64
#define STEPS 32
#define KOUT 2048   // 2*H

typedef unsigned long long ull;
typedef unsigned int u32;

// ---------------- scratch (device globals; no allocation allowed) ----------
__device__ float g_a0[BB * 192];
__device__ float g_h[BB * HH];            // fp32 master hidden state
__device__ float g_gip[4][BB * 3 * HH];   // split-K partials of x @ W_ih^T
__device__ float g_ghp[8][BB * 3 * HH];   // split-K partials of h @ W_hh^T
__device__ float g_qp[8][BB * HH];        // split-K partials of h @ W_a
__device__ ull   g_amax[BB];              // packed (key, 0x7FFFFFFF-n) argmax

// Tiled+swizzled activations: [kchunk][64 rows x 128B(32hi|32lo)] = 8KB blocks
__device__ __align__(16) __nv_bfloat16 g_xt[BB * EE * 2];     // 16 chunks
__device__ __align__(16) __nv_bfloat16 g_ht[BB * HH * 2];     // 32 chunks
__device__ __align__(16) __nv_bfloat16 g_vt[BB * KOUT * 2];   // 64 chunks

// Tiled+swizzled weights: [ntile][kchunk][128 rows x 128B(32hi|32lo)] = 16KB blocks
__device__ __align__(16) __nv_bfloat16 g_Wih[3 * HH * 2 * EE];
__device__ __align__(16) __nv_bfloat16 g_Whh[3 * HH * 2 * HH];
__device__ __align__(16) __nv_bfloat16 g_Wa[HH * 2 * HH];
__device__ __align__(16) __nv_bfloat16 g_Wout[(size_t)VV * 2 * KOUT];

// ====================== PTX helpers ========================================
__device__ __forceinline__ u32 smem_u32(const void* p) {
    u32 a;
    asm("{ .reg .u64 t; cvta.to.shared.u64 t, %1; cvt.u32.u64 %0, t; }"
        : "=r"(a) : "l"(p));
    return a;
}
#define MBAR_INIT(a, c) \
    asm volatile("mbarrier.init.shared.b64 [%0], %1;" :: "r"(a), "r"(c) : "memory")
#define MBAR_EXPECT(a, b) \
    asm volatile("mbarrier.arrive.expect_tx.shared.b64 _, [%0], %1;" :: "r"(a), "r"(b) : "memory")
#define MBAR_ARRIVE(a) \
    asm volatile("mbarrier.arrive.shared.b64 _, [%0];" :: "r"(a) : "memory")
#define FENCE_ASYNC() \
    asm volatile("fence.proxy.async.shared::cta;" ::: "memory")
#define BULK_G2S(dst, src, sz, mb) \
    asm volatile("cp.async.bulk.shared::cluster.global.mbarrier::complete_tx::bytes " \
                 "[%0], [%1], %2, [%3];" \
                 :: "r"(dst), "l"(src), "r"(sz), "r"(mb) : "memory")
#define GDC_WAIT()   asm volatile("griddepcontrol.wait;" ::: "memory")
#define GDC_LAUNCH() asm volatile("griddepcontrol.launch_dependents;" ::: "memory")

__device__ __forceinline__ void mbar_wait(u32 addr, u32 parity) {
    asm volatile(
        "{\n\t.reg .pred P;\n\t"
        "W%=:\n\t"
        "mbarrier.try_wait.parity.shared.b64 P, [%0], %1;\n\t"
        "@P bra D%=;\n\t"
        "bra W%=;\n\t"
        "D%=:\n\t}"
        :: "r"(addr), "r"(parity) : "memory");
}
__device__ __forceinline__ void ldmx4(u32* r, u32 addr) {
    asm volatile("ldmatrix.sync.aligned.m8n8.x4.shared.b16 {%0,%1,%2,%3}, [%4];"
                 : "=r"(r[0]), "=r"(r[1]), "=r"(r[2]), "=r"(r[3]) : "r"(addr));
}
__device__ __forceinline__ void mma16816(float* c, const u32* a, const u32* b) {
    asm volatile(
        "mma.sync.aligned.m16n8k16.row.col.f32.bf16.bf16.f32 "
        "{%0,%1,%2,%3}, {%4,%5,%6,%7}, {%8,%9}, {%0,%1,%2,%3};"
        : "+f"(c[0]), "+f"(c[1]), "+f"(c[2]), "+f"(c[3])
        : "r"(a[0]), "r"(a[1]), "r"(a[2]), "r"(a[3]), "r"(b[0]), "r"(b[1]));
}

// packed argmax key: monotone float map in hi 32, (0x7FFFFFFF - n) in lo 32
__device__ __forceinline__ ull amax_pack(float v, int n) {
    u32 b = __float_as_uint(v);
    u32 key = (b & 0x80000000u) ? ~b : (b | 0x80000000u);
    return ((ull)key << 32) | (ull)(0x7FFFFFFFu - (u32)n);
}

// ===========================================================================
// Split-bf16 HMMA GEMM body (544 threads = 16 consumer warps + 1 producer):
//   C[64, N] = (Ah+Al)[64,Klen] @ (Bh+Bl)[N,Klen]^T (+ bias)
//   = Ah·Bh + Al·Bh + Ah·Bl  (Al·Bl dropped, ~2^-16 relative)
// A/B pre-tiled + SW128-swizzled in GMEM; loaded via cp.async.bulk.
// PDL: producer prefetches B (weights, step-independent) for all 4 stages,
// then griddepcontrol.wait, then issues A (activations). 4-stage pipeline,
// full/empty mbarriers; warp 16 lane 0 is dedicated producer. nk >= 4.
// AM=1: additionally computes per-row argmax of biased output into g_amax.
// ===========================================================================
#define ABLK 8192
#define BBLK 16384
#define STGSZ (ABLK + BBLK)                 // 24576
#define NSTG 4
#define GM_SMEM (NSTG * STGSZ + 64 + 512)   // stages + mbarriers + best[64]

template <int AM>
__device__ __forceinline__ void gemm_body(
    const __nv_bfloat16* __restrict__ At, const __nv_bfloat16* __restrict__ Bt,
    const float* __restrict__ bias, float* __restrict__ C,
    long ldc, int nk, int nkTot, int kcBase, int ntile, char* smem)
{
    const u32 sb = smem_u32(smem);
    const u32 mbF = sb + NSTG * STGSZ;   // full[0..3], 8B each
    const u32 mbE = mbF + 32;            // empty[0..3]
    const int tid = threadIdx.x, wid = tid >> 5, lane = tid & 31;
    const int wm = (wid & 1) * 32;       // warp m offset: 0 or 32
    const int wn = (wid >> 1) * 16;      // warp n offset: 0..112
    const int n_cta = ntile * 128;

    if (tid == 0) {
#pragma unroll
        for (int s = 0; s < NSTG; s++) {
            MBAR_INIT(mbF + 8 * s, 1);
            MBAR_INIT(mbE + 8 * s, 16);
        }
    }
    FENCE_ASYNC();
    __syncthreads();

    float acc[2][2][4] = {};

    if (wid == 16) {
        // ---------------- producer warp (lane 0 only) ----------------
        if (lane == 0) {
            const char* Ab = (const char*)At + (size_t)kcBase * ABLK;
            const char* Bb = (const char*)Bt + ((size_t)ntile * nkTot + kcBase) * BBLK;
            // B prefetch (weights — independent of predecessor kernel)
#pragma unroll
            for (int j = 0; j < NSTG; j++) {
                u32 m = mbF + 8 * j;
                MBAR_EXPECT(m, STGSZ);
                BULK_G2S(sb + j * STGSZ + ABLK, Bb + (size_t)j * BBLK, BBLK, m);
            }
            // activations become valid only after the predecessor completes
            GDC_WAIT();
#pragma unroll
            for (int j = 0; j < NSTG; j++)
                BULK_G2S(sb + j * STGSZ, Ab + (size_t)j * ABLK, ABLK, mbF + 8 * j);
            for (int j = NSTG; j < nk; j++) {
                const int s = j & (NSTG - 1);
                mbar_wait(mbE + 8 * s, ((j - NSTG) >> 2) & 1);
                u32 m = mbF + 8 * s;
                MBAR_EXPECT(m, STGSZ);
                BULK_G2S(sb + s * STGSZ,        Ab + (size_t)j * ABLK, ABLK, m);
                BULK_G2S(sb + s * STGSZ + ABLK, Bb + (size_t)j * BBLK, BBLK, m);
            }
        }
    } else {
        // ---------------- consumer warps ----------------
        const int lrow = lane & 15;
        const int lkof = (lane >> 4) * 16;
        const int a0r = wm + lrow,  a1r = wm + 16 + lrow,  brr = wn + lrow;
        const u32 a0b = a0r * 128,  a0x = (a0r & 7) << 4;
        const u32 a1b = a1r * 128,  a1x = (a1r & 7) << 4;
        const u32 brb = brr * 128,  brx = (brr & 7) << 4;

        for (int j = 0; j < nk; j++) {
            const int s = j & (NSTG - 1);
            mbar_wait(mbF + 8 * s, (j >> 2) & 1);

            const u32 bbA = sb + s * STGSZ;
            const u32 bbB = bbA + ABLK;
#pragma unroll
            for (int ks = 0; ks < 2; ks++) {
                const u32 o = ks * 32 + lkof;
                u32 ah[2][4], al[2][4], bh[4], bl[4];
                ldmx4(ah[0], bbA + a0b + (o ^ a0x));
                ldmx4(ah[1], bbA + a1b + (o ^ a1x));
                ldmx4(al[0], bbA + a0b + ((o + 64) ^ a0x));
                ldmx4(al[1], bbA + a1b + ((o + 64) ^ a1x));
                ldmx4(bh,    bbB + brb + (o ^ brx));
                ldmx4(bl,    bbB + brb + ((o + 64) ^ brx));

                u32 b0h[2] = { bh[0], bh[2] };
                u32 b1h[2] = { bh[1], bh[3] };
                u32 b0l[2] = { bl[0], bl[2] };
                u32 b1l[2] = { bl[1], bl[3] };
#pragma unroll
                for (int mt = 0; mt < 2; mt++) {
                    float* c0 = acc[mt][0];
                    float* c1 = acc[mt][1];
                    mma16816(c0, ah[mt], b0h);
                    mma16816(c1, ah[mt], b1h);
                    mma16816(c0, al[mt], b0h);
                    mma16816(c1, al[mt], b1h);
                    mma16816(c0, ah[mt], b0l);
                    mma16816(c1, ah[mt], b1l);
                }
            }
            if (lane == 0) MBAR_ARRIVE(mbE + 8 * s);
        }
    }

    GDC_LAUNCH();   // allow successor kernel to launch during our epilogue

    // ------------- epilogue -------------
    ull* best = reinterpret_cast<ull*>(smem + NSTG * STGSZ + 64);
    if (AM) {
        if (tid < 64) best[tid] = 0;
        __syncthreads();
    }

    if (wid < 16) {
#pragma unroll
        for (int mt = 0; mt < 2; mt++) {
            int m = wm + mt * 16 + (lane >> 2);
            ull p0 = 0, p1 = 0;
#pragma unroll
            for (int t = 0; t < 2; t++) {
                int n = n_cta + wn + t * 8 + 2 * (lane & 3);
                float* a = acc[mt][t];
                float b0 = bias ? bias[n] : 0.f;
                float b1 = bias ? bias[n + 1] : 0.f;
                float2 v0 = { a[0] + b0, a[1] + b1 };
                float2 v1 = { a[2] + b0, a[3] + b1 };
                *reinterpret_cast<float2*>(C + (size_t)m * ldc + n) = v0;
                *reinterpret_cast<float2*>(C + (size_t)(m + 8) * ldc + n) = v1;
                if (AM) {
                    ull q0 = amax_pack(v0.x, n), q1 = amax_pack(v0.y, n + 1);
                    p0 = max(p0, max(q0, q1));
                    ull q2 = amax_pack(v1.x, n), q3 = amax_pack(v1.y, n + 1);
                    p1 = max(p1, max(q2, q3));
                }
            }
            if (AM) {
#pragma unroll
                for (int o = 1; o < 4; o <<= 1) {
                    p0 = max(p0, __shfl_xor_sync(0xFFFFFFFFu, p0, o));
                    p1 = max(p1, __shfl_xor_sync(0xFFFFFFFFu, p1, o));
                }
                if ((lane & 3) == 0) {
                    atomicMax(&best[m], p0);
                    atomicMax(&best[m + 8], p1);
                }
            }
        }
    }
    if (AM) {
        __syncthreads();
        if (tid < 64) atomicMax(&g_amax[tid], best[tid]);
    }
}

// logits GEMM: 250 CTAs, fused argmax
__global__ __launch_bounds__(544, 2)
void gemm_logits(const __nv_bfloat16* __restrict__ At, const __nv_bfloat16* __restrict__ Bt,
                 const float* __restrict__ bias, float* __restrict__ C, long ldc)
{
    extern __shared__ char smem[];
    gemm_body<1>(At, Bt, bias, C, ldc, KOUT / 32, KOUT / 32, 0, blockIdx.x, smem);
}

// q-GEMM 8-way split-K: 64 CTAs; slice s covers chunks [s*4, s*4+4)
__global__ __launch_bounds__(544, 2)
void gemm_q(const __nv_bfloat16* __restrict__ ht, const __nv_bfloat16* __restrict__ Wa)
{
    extern __shared__ char smem[];
    int s = blockIdx.x >> 3, nt = blockIdx.x & 7;
    gemm_body<0>(ht, Wa, nullptr, g_qp[s], HH, 4, HH / 32, s * 4, nt, smem);
}

// fused gi + gh: gi 4-way split (96 CTAs), gh 8-way split (192 CTAs) = 288 CTAs
__global__ __launch_bounds__(544, 2)
void gemm_gigh(const __nv_bfloat16* __restrict__ xt, const __nv_bfloat16* __restrict__ Wih,
               const __nv_bfloat16* __restrict__ ht, const __nv_bfloat16* __restrict__ Whh)
{
    extern __shared__ char smem[];
    int bid = blockIdx.x;
    if (bid < 96) {
        int s = bid / 24, nt = bid % 24;   // gi: K=512 -> 4 slices x 4 chunks
        gemm_body<0>(xt, Wih, nullptr, g_gip[s], 3 * HH, 4, EE / 32, s * 4, nt, smem);
    } else {
        bid -= 96;
        int s = bid / 24, nt = bid % 24;   // gh: K=1024 -> 8 slices x 4 chunks
        gemm_body<0>(ht, Whh, nullptr, g_ghp[s], 3 * HH, 4, HH / 32, s * 4, nt, smem);
    }
}

// ===================== split + tiled-store helpers =========================
__device__ __forceinline__ void split2(float v, __nv_bfloat16& h, __nv_bfloat16& l) {
    h = __float2bfloat16(v);
    l = __float2bfloat16(v - __bfloat162float(h));
}

// store one activation element into tiled+swizzled layout (8KB A-blocks)
__device__ __forceinline__ void store_act(__nv_bfloat16* base, int kc, int r, int c, float v) {
    __nv_bfloat16 h, l; split2(v, h, l);
    u32 xm = (r & 7) << 4;
    char* p = (char*)base + (size_t)kc * ABLK + r * 128;
    *reinterpret_cast<__nv_bfloat16*>(p + ((c * 2) ^ xm)) = h;
    *reinterpret_cast<__nv_bfloat16*>(p + ((64 + c * 2) ^ xm)) = l;
}

// store one weight element into tiled+swizzled layout (16KB B-blocks)
__device__ __forceinline__ void store_w(__nv_bfloat16* base, int nkTot, int n, int k, float v) {
    __nv_bfloat16 h, l; split2(v, h, l);
    int nt = n >> 7, r = n & 127, kc = k >> 5, c = k & 31;
    u32 xm = (r & 7) << 4;
    char* p = (char*)base + ((size_t)nt * nkTot + kc) * BBLK + r * 128;
    *reinterpret_cast<__nv_bfloat16*>(p + ((c * 2) ^ xm)) = h;
    *reinterpret_cast<__nv_bfloat16*>(p + ((64 + c * 2) ^ xm)) = l;
}

// elementwise: src already [N,K]
__device__ __forceinline__ void esplit_blk(const float* src, __nv_bfloat16* dc,
                                           int K, int bi, int tid)
{
    int i = bi * 256 + tid;
    store_w(dc, K >> 5, i / K, i % K, src[i]);
}

// transpose 32x32 tile: src [K,N] fp32 -> tiled [N-major] layout
__device__ __forceinline__ void tsplit_blk(const float* src, __nv_bfloat16* dc,
                                           int K, int N, int bx, int by, int tid)
{
    __shared__ float t[32][33];
    int k0 = by * 32, n0 = bx * 32;
    int tx = tid & 31, ty = tid >> 5;   // 32 x 8
#pragma unroll
    for (int i = ty; i < 32; i += 8)
        t[i][tx] = src[(size_t)(k0 + i) * N + n0 + tx];
    __syncthreads();
#pragma unroll
    for (int i = ty; i < 32; i += 8)
        store_w(dc, K >> 5, n0 + i, k0 + tx, t[tx][i]);
}

#define NB_WIH  6144    // 3*HH*EE / 256
#define NB_WHH 12288    // 3*HH*HH / 256
#define NB_WA   1024    // (HH/32)*(HH/32)
#define NB_WOUT 64000   // (VV/32)*(KOUT/32)
#define NB_CONV (NB_WIH + NB_WHH + NB_WA + NB_WOUT)

__global__ __launch_bounds__(256)
void convert_all(const float* __restrict__ W_ih, const float* __restrict__ W_hh,
                 const float* __restrict__ W_a,  const float* __restrict__ W_out)
{
    int b = blockIdx.x, tid = threadIdx.x;
    if (b < NB_WIH) {
        esplit_blk(W_ih, g_Wih, EE, b, tid);
    } else if (b < NB_WIH + NB_WHH) {
        esplit_blk(W_hh, g_Whh, HH, b - NB_WIH, tid);
    } else if (b < NB_WIH + NB_WHH + NB_WA) {
        int bi = b - NB_WIH - NB_WHH;
        tsplit_blk(W_a, g_Wa, HH, HH, bi % 32, bi / 32, tid);
    } else {
        int bi = b - NB_WIH - NB_WHH - NB_WA;
        tsplit_blk(W_out, g_Wout, KOUT, VV, bi % (VV / 32), bi / (VV / 32), tid);
    }
}

// ======================= init kernels ======================================
__global__ void build_init(const float* __restrict__ latent,
                           const int* __restrict__ style,
                           const float* __restrict__ style_emb,
                           const float* __restrict__ emb)
{
    int idx = blockIdx.x * blockDim.x + threadIdx.x;
    if (idx < BB * 192) {
        int b = idx / 192, k = idx - b * 192;
        g_a0[idx] = (k < 128) ? latent[b * 128 + k]
                              : style_emb[style[b] * 64 + (k - 128)];
    } else {
        int i = idx - BB * 192;
        if (i < BB * EE) {
            int b = i >> 9, e = i & (EE - 1);
            float v = emb[EE /* BOS=1 row */ + e];
            store_act(g_xt, e >> 5, b, e & 31, v);
        }
    }
}

// h = a0 @ W_l2h + b (fp32 FFMA; also emits tiled split-bf16 h)
__global__ __launch_bounds__(128)
void gemm_init(const float* __restrict__ A, int lda,
               const float* __restrict__ Bm, const float* __restrict__ bias,
               float* __restrict__ C, int N, int K)
{
    __shared__ float As[16][68];
    __shared__ float Bs[16][132];
    const int tid = threadIdx.x;
    const int n0 = blockIdx.x * 128;
    const int tm = (tid >> 4) << 3, tn = (tid & 15) << 3;
    float acc[8][8] = {};
    for (int k0 = 0; k0 < K; k0 += 16) {
        {
            int k = tid & 15, m = tid >> 4;
#pragma unroll
            for (int i = 0; i < 8; i++)
                As[k][m + i * 8] = A[(m + i * 8) * lda + k0 + k];
        }
        {
            int w = tid >> 5, n4 = (tid & 31) << 2;
#pragma unroll
            for (int kb = 0; kb < 4; kb++) {
                int k = kb * 4 + w;
                *reinterpret_cast<float4*>(&Bs[k][n4]) =
                    *reinterpret_cast<const float4*>(&Bm[(size_t)(k0 + k) * N + n0 + n4]);
            }
        }
        __syncthreads();
#pragma unroll
        for (int kk = 0; kk < 16; kk++) {
#pragma unroll
            for (int i = 0; i < 8; i++) {
                float a = As[kk][tm + i];
#pragma unroll
                for (int j = 0; j < 8; j++) acc[i][j] += a * Bs[kk][tn + j];
            }
        }
        __syncthreads();
    }
#pragma unroll
    for (int i = 0; i < 8; i++)
#pragma unroll
        for (int j = 0; j < 8; j++) {
            int n = n0 + tn + j;
            float v = acc[i][j] + (bias ? bias[n] : 0.f);
            int m = tm + i;
            C[(size_t)m * N + n] = v;
            store_act(g_ht, n >> 5, m, n & 31, v);
        }
}

// ========================= per-step small kernels ==========================
__global__ void gru_gates(const float* __restrict__ b_ih, const float* __restrict__ b_hh)
{
    GDC_WAIT();
    int idx = blockIdx.x * blockDim.x + threadIdx.x;   // 64*1024
    if (idx < BB) g_amax[idx] = 0;   // reset fused-argmax slots for this step
    int b = idx >> 10, j = idx & 1023;
    int base = b * 3 * HH + j;
    float ir = b_ih[j], iz = b_ih[j + HH], in = b_ih[j + 2 * HH];
    float hr = b_hh[j], hz = b_hh[j + HH], hn = b_hh[j + 2 * HH];
#pragma unroll
    for (int s = 0; s < 4; s++) {
        ir += g_gip[s][base];
        iz += g_gip[s][base + HH];
        in += g_gip[s][base + 2 * HH];
    }
#pragma unroll
    for (int s = 0; s < 8; s++) {
        hr += g_ghp[s][base];
        hz += g_ghp[s][base + HH];
        hn += g_ghp[s][base + 2 * HH];
    }
    float r = 1.f / (1.f + expf(-(ir + hr)));
    float z = 1.f / (1.f + expf(-(iz + hz)));
    float n = tanhf(in + r * hn);
    float hnew = (1.f - z) * n + z * g_h[idx];
    g_h[idx] = hnew;
    GDC_LAUNCH();
    int kc = j >> 5, c = j & 31;
    store_act(g_ht, kc, b, c, hnew);
    store_act(g_vt, kc, b, c, hnew);   // vcat chunks 0..31 = h
}

__global__ __launch_bounds__(512)
void attn_kernel(const float* __restrict__ enc)
{
    int b = blockIdx.x;
    int tid = threadIdx.x;              // 512
    __shared__ float s_q[HH];
    __shared__ float s_scores[TENC];
    __shared__ float s_attn[TENC];

    GDC_WAIT();
    for (int i = tid; i < HH; i += 512) {
        int o = b * HH + i;
        float q = 0.f;
#pragma unroll
        for (int s = 0; s < 8; s++) q += g_qp[s][o];
        s_q[i] = q;
    }
    __syncthreads();

    int warp = tid >> 5, lane = tid & 31;
    for (int t = warp; t < TENC; t += 16) {
        const float* e = enc + ((size_t)b * TENC + t) * HH;
        float s = 0.f;
        for (int h = lane; h < HH; h += 32) s += s_q[h] * e[h];
#pragma unroll
        for (int o = 16; o; o >>= 1) s += __shfl_xor_sync(0xFFFFFFFFu, s, o);
        if (lane == 0) s_scores[t] = s;
    }
    __syncthreads();

    float mx = -1e30f;
    for (int t = 0; t < TENC; t++) mx = fmaxf(mx, s_scores[t]);
    if (tid < TENC) s_attn[tid] = expf(s_scores[tid] - mx);
    __syncthreads();
    float ssum = 0.f;
    for (int t = 0; t < TENC; t++) ssum += s_attn[t];
    float inv = 1.f / ssum;
    GDC_LAUNCH();

    for (int h = tid; h < HH; h += 512) {
        float c = 0.f;
        const float* eb = enc + (size_t)b * TENC * HH + h;
#pragma unroll 8
        for (int t = 0; t < TENC; t++) c += s_attn[t] * eb[(size_t)t * HH];
        c *= inv;
        store_act(g_vt, 32 + (h >> 5), b, h & 31, c);   // vcat chunks 32..63 = ctx
    }
}

// decode g_amax -> token, gather embedding into g_xt
__global__ __launch_bounds__(128)
void embed_next(const float* __restrict__ emb)
{
    GDC_WAIT();
    int b = blockIdx.x;
    int tid = threadIdx.x;
    int tok = 0x7FFFFFFF - (int)(u32)(g_amax[b] & 0xFFFFFFFFull);
    GDC_LAUNCH();
    for (int e = tid; e < EE; e += 128) {
        float v = emb[(size_t)tok * EE + e];
        store_act(g_xt, e >> 5, b, e & 31, v);
    }
}

// ===========================================================================
extern "C" void kernel_launch(void* const* d_in, const int* in_sizes, int n_in,
                              void* d_out, int out_size)
{
    const float* latent    = (const float*)d_in[0];
    const int*   style     = (const int*)  d_in[1];
    const float* enc       = (const float*)d_in[2];
    const float* emb       = (const float*)d_in[4];
    const float* style_emb = (const float*)d_in[5];
    const float* W_l2h     = (const float*)d_in[6];
    const float* b_l2h     = (const float*)d_in[7];
    const float* W_ih      = (const float*)d_in[8];
    const float* W_hh      = (const float*)d_in[9];
    const float* b_ih      = (const float*)d_in[10];
    const float* b_hh      = (const float*)d_in[11];
    const float* W_a       = (const float*)d_in[12];
    const float* W_out     = (const float*)d_in[13];
    const float* b_out     = (const float*)d_in[14];
    float* out = (float*)d_out;

    cudaFuncSetAttribute(gemm_logits, cudaFuncAttributeMaxDynamicSharedMemorySize, GM_SMEM);
    cudaFuncSetAttribute(gemm_q,      cudaFuncAttributeMaxDynamicSharedMemorySize, GM_SMEM);
    cudaFuncSetAttribute(gemm_gigh,   cudaFuncAttributeMaxDynamicSharedMemorySize, GM_SMEM);

    __nv_bfloat16 *pWih, *pWhh, *pWa, *pWout, *pxt, *pht, *pvt;
    float *p_a0, *p_h;
    cudaGetSymbolAddress((void**)&pWih,  g_Wih);
    cudaGetSymbolAddress((void**)&pWhh,  g_Whh);
    cudaGetSymbolAddress((void**)&pWa,   g_Wa);
    cudaGetSymbolAddress((void**)&pWout, g_Wout);
    cudaGetSymbolAddress((void**)&pxt,   g_xt);
    cudaGetSymbolAddress((void**)&pht,   g_ht);
    cudaGetSymbolAddress((void**)&pvt,   g_vt);
    cudaGetSymbolAddress((void**)&p_a0,  g_a0);
    cudaGetSymbolAddress((void**)&p_h,   g_h);

    // PDL launch attribute (programmatic stream serialization)
    cudaLaunchAttribute pdlAttr;
    pdlAttr.id = cudaLaunchAttributeProgrammaticStreamSerialization;
    pdlAttr.val.programmaticStreamSerializationAllowed = 1;
    auto cfg = [&](int grid, int block, size_t smem) {
        cudaLaunchConfig_t c = {};
        c.gridDim = dim3(grid); c.blockDim = dim3(block);
        c.dynamicSmemBytes = smem; c.stream = 0;
        c.attrs = &pdlAttr; c.numAttrs = 1;
        return c;
    };

    // launch 0: all weight conversion (tiled + swizzled layout)
    convert_all<<<NB_CONV, 256>>>(W_ih, W_hh, W_a, W_out);
    // launch 1: a0 + x0
    build_init<<<(BB * 192 + BB * EE + 255) / 256, 256>>>(latent, style, style_emb, emb);
    // launch 2: h init (+ tiled split)
    gemm_init<<<HH / 128, 128>>>(p_a0, 192, W_l2h, b_l2h, p_h, HH, 192);

    // decode loop (all step kernels use PDL)
    for (int t = 0; t < STEPS; t++) {
        {
            cudaLaunchConfig_t c = cfg(288, 544, GM_SMEM);
            cudaLaunchKernelEx(&c, gemm_gigh,
                               (const __nv_bfloat16*)pxt, (const __nv_bfloat16*)pWih,
                               (const __nv_bfloat16*)pht, (const __nv_bfloat16*)pWhh);
        }
        {
            cudaLaunchConfig_t c = cfg((BB * HH) / 256, 256, 0);
            cudaLaunchKernelEx(&c, gru_gates, b_ih, b_hh);
        }
        {
            cudaLaunchConfig_t c = cfg(64, 544, GM_SMEM);
            cudaLaunchKernelEx(&c, gemm_q,
                               (const __nv_bfloat16*)pht, (const __nv_bfloat16*)pWa);
        }
        {
            cudaLaunchConfig_t c = cfg(BB, 512, 0);
            cudaLaunchKernelEx(&c, attn_kernel, enc);
        }
        {
            cudaLaunchConfig_t c = cfg(VV / 128, 544, GM_SMEM);
            cudaLaunchKernelEx(&c, gemm_logits,
                               (const __nv_bfloat16*)pvt, (const __nv_bfloat16*)pWout,
                               b_out, out + (size_t)t * VV, (long)STEPS * VV);
        }
        if (t < STEPS - 1) {
            cudaLaunchConfig_t c = cfg(BB, 128, 0);
            cudaLaunchKernelEx(&c, embed_next, emb);
        }
    }
}